// round 8
// baseline (speedup 1.0000x reference)
#include <cuda_runtime.h>

#define Ll 8
#define Kk 35
#define Sq 101
#define NP 51          // key pairs (50 full + 1 zero-padded odd slot)
#define PRS 36         // floats per pair row (32 used + 4 pad) = 144B, 16B aligned
#define BLOCK 128

#define KOFF 0
#define VOFF (NP * PRS)            // 1836
#define SKVTOT (2 * NP * PRS)      // 3672 floats (aliases x staging, 3500)

// shared-weight buffer offsets (floats)
#define OWQKV 0
#define OBQKV 768
#define OWO   816
#define OBO   1072
#define OW1   1088
#define OB1   1344
#define OW2   1360
#define OB2   1616
#define OG1   1632
#define OBE1  1648
#define OG2   1664
#define OBE2  1680
#define WTOT  1696

typedef unsigned long long u64;

__device__ __forceinline__ u64 pk2(float lo, float hi) {
    u64 r; asm("mov.b64 %0, {%1, %2};" : "=l"(r) : "f"(lo), "f"(hi)); return r;
}
__device__ __forceinline__ void upk2(u64 v, float& lo, float& hi) {
    asm("mov.b64 {%0, %1}, %2;" : "=f"(lo), "=f"(hi) : "l"(v));
}
__device__ __forceinline__ u64 fma2_(u64 a, u64 b, u64 c) {
    u64 d; asm("fma.rn.f32x2 %0, %1, %2, %3;" : "=l"(d) : "l"(a), "l"(b), "l"(c)); return d;
}
__device__ __forceinline__ u64 mul2_(u64 a, u64 b) {
    u64 d; asm("mul.rn.f32x2 %0, %1, %2;" : "=l"(d) : "l"(a), "l"(b)); return d;
}
__device__ __forceinline__ u64 add2_(u64 a, u64 b) {
    u64 d; asm("add.rn.f32x2 %0, %1, %2;" : "=l"(d) : "l"(a), "l"(b)); return d;
}
__device__ __forceinline__ float ex2_(float x) {
    float e; asm("ex2.approx.f32 %0, %1;" : "=f"(e) : "f"(x)); return e;
}

// dot of packed 16-vector a2[8] with a 16-float 16B-aligned row
__device__ __forceinline__ float dot16p(const u64* a2, const float* w) {
    const ulonglong2* w2 = reinterpret_cast<const ulonglong2*>(w);
    ulonglong2 p0 = w2[0], p1 = w2[1], p2 = w2[2], p3 = w2[3];
    u64 acc = mul2_(a2[0], p0.x);
    acc = fma2_(a2[1], p0.y, acc);
    acc = fma2_(a2[2], p1.x, acc);
    acc = fma2_(a2[3], p1.y, acc);
    acc = fma2_(a2[4], p2.x, acc);
    acc = fma2_(a2[5], p2.y, acc);
    acc = fma2_(a2[6], p3.x, acc);
    acc = fma2_(a2[7], p3.y, acc);
    float lo, hi; upk2(acc, lo, hi);
    return lo + hi;
}

__device__ __forceinline__ void ln16p(u64* io, const float* g, const float* b) {
    u64 s2 = io[0];
    #pragma unroll
    for (int i = 1; i < 8; i++) s2 = add2_(s2, io[i]);
    float slo, shi; upk2(s2, slo, shi);
    float mu = (slo + shi) * (1.f / 16.f);
    u64 nm2 = pk2(-mu, -mu);
    u64 c[8];
    #pragma unroll
    for (int i = 0; i < 8; i++) c[i] = add2_(io[i], nm2);
    u64 v2 = mul2_(c[0], c[0]);
    #pragma unroll
    for (int i = 1; i < 8; i++) v2 = fma2_(c[i], c[i], v2);
    float vlo, vhi; upk2(v2, vlo, vhi);
    float inv = rsqrtf((vlo + vhi) * (1.f / 16.f) + 1e-5f);
    u64 inv2 = pk2(inv, inv);
    const ulonglong2* g2 = reinterpret_cast<const ulonglong2*>(g);
    const ulonglong2* b2 = reinterpret_cast<const ulonglong2*>(b);
    #pragma unroll
    for (int j = 0; j < 4; j++) {
        ulonglong2 gg = g2[j], bb = b2[j];
        io[2*j]   = fma2_(mul2_(c[2*j],   inv2), gg.x, bb.x);
        io[2*j+1] = fma2_(mul2_(c[2*j+1], inv2), gg.y, bb.y);
    }
}

__global__ __launch_bounds__(BLOCK, 6) void TorrinE0_kernel(
    const float* __restrict__ x,
    const float* __restrict__ conv_w,
    const float* __restrict__ conv_b,
    const float* __restrict__ cls_emb,
    const float* __restrict__ Wqkv,
    const float* __restrict__ bqkv,
    const float* __restrict__ Wo,
    const float* __restrict__ bo,
    const float* __restrict__ W1,
    const float* __restrict__ b1,
    const float* __restrict__ W2,
    const float* __restrict__ b2,
    const float* __restrict__ ln1_g, const float* __restrict__ ln1_b,
    const float* __restrict__ ln2_g, const float* __restrict__ ln2_b,
    const float* __restrict__ lnf_g, const float* __restrict__ lnf_b,
    const float* __restrict__ end_w, const float* __restrict__ end_b,
    const float* __restrict__ head_w, const float* __restrict__ head_b,
    float* __restrict__ out)
{
    __shared__ __align__(16) float skv[SKVTOT];      // kT | vT (aliases x staging)
    __shared__ __align__(16) float sw[WTOT];
    __shared__ __align__(16) u64 shh[102 * 9];       // h2 stash, stride 9 u64
    __shared__ float sred[4];
    __shared__ float scls[16];

    const int b   = blockIdx.x;
    const int tid = threadIdx.x;
    const bool tok = (tid <= 100);

    // ---- stage x row + conv weights ----
    const float* xr = x + (size_t)b * 3500;
    for (int i = tid; i < 875; i += BLOCK)
        ((float4*)skv)[i] = ((const float4*)xr)[i];
    for (int i = tid; i < 140; i += BLOCK)
        ((float4*)sw)[i] = ((const float4*)conv_w)[i];
    if (tid < 16) sw[560 + tid] = conv_b[tid];
    __syncthreads();

    // ---- conv patchify -> packed h in registers ----
    u64 h2[8];
    if (tid == 0) {
        #pragma unroll
        for (int i = 0; i < 8; i++) h2[i] = pk2(cls_emb[2*i], cls_emb[2*i+1]);
    } else if (tok) {
        const float* ps = &skv[(tid - 1) * Kk];
        #pragma unroll
        for (int i = 0; i < 8; i++) {
            float a0 = sw[560 + 2*i], a1 = sw[560 + 2*i + 1];
            for (int k = 0; k < Kk; k++) {
                float p = ps[k];
                a0 += p * sw[(2*i) * Kk + k];
                a1 += p * sw[(2*i+1) * Kk + k];
            }
            h2[i] = pk2(a0, a1);
        }
    }
    __syncthreads();   // conv reads done before k/v overwrite

    const float QS = 0.70710678118654752f * 1.44269504088896340f;  // scale * log2(e)
    const int wbase = (tid >> 1) * PRS + (tid & 1);   // col parity = key parity

    #pragma unroll 1
    for (int l = 0; l < Ll; l++) {
        // ---- stage layer weights ----
        for (int i = tid; i < 192; i += BLOCK)
            ((float4*)&sw[OWQKV])[i] = ((const float4*)(Wqkv + l*768))[i];
        for (int i = tid; i < 64; i += BLOCK) {
            ((float4*)&sw[OWO])[i] = ((const float4*)(Wo + l*256))[i];
            ((float4*)&sw[OW1])[i] = ((const float4*)(W1 + l*256))[i];
            ((float4*)&sw[OW2])[i] = ((const float4*)(W2 + l*256))[i];
        }
        if (tid < 48) sw[OBQKV + tid] = bqkv[l*48 + tid];
        if (tid < 16) {
            sw[OBO  + tid] = bo[l*16 + tid];
            sw[OB1  + tid] = b1[l*16 + tid];
            sw[OB2  + tid] = b2[l*16 + tid];
            sw[OG1  + tid] = ln1_g[l*16 + tid];
            sw[OBE1 + tid] = ln1_b[l*16 + tid];
            sw[OG2  + tid] = ln2_g[l*16 + tid];
            sw[OBE2 + tid] = ln2_b[l*16 + tid];
        }
        __syncthreads();

        // ---- qkv projection: q in regs (broadcast pairs, pre-scaled), k/v transposed to smem ----
        u64 qb0[8], qb1[8];
        if (tok) {
            #pragma unroll
            for (int h = 0; h < 8; h++) {
                float q0 = sw[OBQKV + 2*h]     + dot16p(h2, &sw[OWQKV + (2*h)*16]);
                float q1 = sw[OBQKV + 2*h + 1] + dot16p(h2, &sw[OWQKV + (2*h+1)*16]);
                q0 *= QS; q1 *= QS;
                qb0[h] = pk2(q0, q0);
                qb1[h] = pk2(q1, q1);
                float k0 = sw[OBQKV + 16 + 2*h]     + dot16p(h2, &sw[OWQKV + (16 + 2*h)*16]);
                float k1 = sw[OBQKV + 16 + 2*h + 1] + dot16p(h2, &sw[OWQKV + (17 + 2*h)*16]);
                skv[KOFF + wbase + 4*h]     = k0;
                skv[KOFF + wbase + 4*h + 2] = k1;
                float v0 = sw[OBQKV + 32 + 2*h]     + dot16p(h2, &sw[OWQKV + (32 + 2*h)*16]);
                float v1 = sw[OBQKV + 32 + 2*h + 1] + dot16p(h2, &sw[OWQKV + (33 + 2*h)*16]);
                skv[VOFF + wbase + 4*h]     = v0;
                skv[VOFF + wbase + 4*h + 2] = v1;
            }
        } else if (tid == 101) {
            // zero-pad the odd slot of pair 50: exp(0)=1 corrected post-loop; v=0
            #pragma unroll
            for (int h = 0; h < 8; h++) {
                skv[KOFF + wbase + 4*h]     = 0.f;
                skv[KOFF + wbase + 4*h + 2] = 0.f;
                skv[VOFF + wbase + 4*h]     = 0.f;
                skv[VOFF + wbase + 4*h + 2] = 0.f;
            }
        }
        __syncthreads();

        // ---- attention over 51 key-pairs ----
        if (tok) {
            u64* st = &shh[tid * 9];
            #pragma unroll
            for (int i = 0; i < 8; i++) st[i] = h2[i];   // free regs for hot loop

            u64 ssum2[8], ctx0[8], ctx1[8];
            #pragma unroll
            for (int i = 0; i < 8; i++) { ssum2[i] = 0ULL; ctx0[i] = 0ULL; ctx1[i] = 0ULL; }

            const ulonglong2* kpp = (const ulonglong2*)&skv[KOFF];
            const ulonglong2* vpp = (const ulonglong2*)&skv[VOFF];
            #pragma unroll 1
            for (int p = 0; p < NP; p++) {
                #pragma unroll
                for (int h = 0; h < 8; h++) {
                    ulonglong2 kk = kpp[h];            // (k0e,k0o),(k1e,k1o)
                    u64 d2 = fma2_(qb1[h], kk.y, mul2_(qb0[h], kk.x));   // (se,so)
                    float se, so; upk2(d2, se, so);
                    float ee = ex2_(se), eo = ex2_(so);
                    u64 ep = pk2(ee, eo);
                    ssum2[h] = add2_(ssum2[h], ep);
                    ulonglong2 vv = vpp[h];
                    ctx0[h] = fma2_(ep, vv.x, ctx0[h]);
                    ctx1[h] = fma2_(ep, vv.y, ctx1[h]);
                }
                kpp += 9; vpp += 9;
            }

            u64 ctxp[8];
            #pragma unroll
            for (int h = 0; h < 8; h++) {
                float slo, shi; upk2(ssum2[h], slo, shi);
                float r = __fdividef(1.f, slo + shi - 1.f);   // remove pad's exp(0)=1
                float a0, a1, b0v, b1v;
                upk2(ctx0[h], a0, a1);
                upk2(ctx1[h], b0v, b1v);
                ctxp[h] = pk2((a0 + a1) * r, (b0v + b1v) * r);
            }

            #pragma unroll
            for (int i = 0; i < 8; i++) h2[i] = st[i];   // restore h

            // out projection + residual + LN1
            u64 nh2[8];
            #pragma unroll
            for (int o = 0; o < 8; o++) {
                float d0 = sw[OBO + 2*o]     + dot16p(ctxp, &sw[OWO + (2*o)*16]);
                float d1 = sw[OBO + 2*o + 1] + dot16p(ctxp, &sw[OWO + (2*o+1)*16]);
                nh2[o] = add2_(h2[o], pk2(d0, d1));
            }
            ln16p(nh2, &sw[OG1], &sw[OBE1]);
            #pragma unroll
            for (int i = 0; i < 8; i++) h2[i] = nh2[i];

            // FFN
            u64 ff2[8];
            #pragma unroll
            for (int f = 0; f < 8; f++) {
                float f0 = fmaxf(sw[OB1 + 2*f]     + dot16p(h2, &sw[OW1 + (2*f)*16]),   0.f);
                float f1 = fmaxf(sw[OB1 + 2*f + 1] + dot16p(h2, &sw[OW1 + (2*f+1)*16]), 0.f);
                ff2[f] = pk2(f0, f1);
            }
            #pragma unroll
            for (int o = 0; o < 8; o++) {
                float d0 = sw[OB2 + 2*o]     + dot16p(ff2, &sw[OW2 + (2*o)*16]);
                float d1 = sw[OB2 + 2*o + 1] + dot16p(ff2, &sw[OW2 + (2*o+1)*16]);
                nh2[o] = add2_(h2[o], pk2(d0, d1));
            }
            ln16p(nh2, &sw[OG2], &sw[OBE2]);
            #pragma unroll
            for (int i = 0; i < 8; i++) h2[i] = nh2[i];
        }
        __syncthreads();   // all reads of skv/sw done before next layer
    }

    // ---- final LN on CLS token + head ----
    if (tid == 0) {
        float hv[16];
        #pragma unroll
        for (int i = 0; i < 8; i++) upk2(h2[i], hv[2*i], hv[2*i+1]);
        float mu = 0.f;
        #pragma unroll
        for (int d = 0; d < 16; d++) mu += hv[d];
        mu *= (1.f/16.f);
        float var = 0.f;
        #pragma unroll
        for (int d = 0; d < 16; d++) { float c = hv[d] - mu; var += c*c; }
        var *= (1.f/16.f);
        float inv = rsqrtf(var + 1e-5f);
        #pragma unroll
        for (int d = 0; d < 16; d++)
            scls[d] = (hv[d] - mu) * inv * lnf_g[d] + lnf_b[d];
    }
    __syncthreads();

    float part = 0.f;
    if (tid < 100) {
        u64 c2[8];
        #pragma unroll
        for (int i = 0; i < 8; i++) c2[i] = pk2(scls[2*i], scls[2*i+1]);
        float acc = end_b[tid] + dot16p(c2, end_w + tid * 16);
        part = acc * head_w[tid];
    }
    #pragma unroll
    for (int off = 16; off > 0; off >>= 1)
        part += __shfl_down_sync(0xffffffffu, part, off);
    if ((tid & 31) == 0) sred[tid >> 5] = part;
    __syncthreads();
    if (tid == 0) {
        float z = sred[0] + sred[1] + sred[2] + sred[3] + head_b[0];
        out[b] = 1.f / (1.f + ex2_(-z * 1.44269504088896340f));
    }
}

extern "C" void kernel_launch(void* const* d_in, const int* in_sizes, int n_in,
                              void* d_out, int out_size) {
    const float* x      = (const float*)d_in[0];
    const float* conv_w = (const float*)d_in[1];
    const float* conv_b = (const float*)d_in[2];
    const float* cls_e  = (const float*)d_in[3];
    const float* Wqkv   = (const float*)d_in[4];
    const float* bqkv   = (const float*)d_in[5];
    const float* Wo     = (const float*)d_in[6];
    const float* bo     = (const float*)d_in[7];
    const float* W1     = (const float*)d_in[8];
    const float* b1     = (const float*)d_in[9];
    const float* W2     = (const float*)d_in[10];
    const float* b2     = (const float*)d_in[11];
    const float* ln1_g  = (const float*)d_in[12];
    const float* ln1_b  = (const float*)d_in[13];
    const float* ln2_g  = (const float*)d_in[14];
    const float* ln2_b  = (const float*)d_in[15];
    const float* lnf_g  = (const float*)d_in[16];
    const float* lnf_b  = (const float*)d_in[17];
    const float* end_w  = (const float*)d_in[18];
    const float* end_b  = (const float*)d_in[19];
    const float* head_w = (const float*)d_in[20];
    const float* head_b = (const float*)d_in[21];

    int B = out_size;   // 2048
    TorrinE0_kernel<<<B, BLOCK>>>(x, conv_w, conv_b, cls_e, Wqkv, bqkv, Wo, bo,
                                  W1, b1, W2, b2, ln1_g, ln1_b, ln2_g, ln2_b,
                                  lnf_g, lnf_b, end_w, end_b, head_w, head_b,
                                  (float*)d_out);
}

// round 9
// speedup vs baseline: 1.1744x; 1.1744x over previous
#include <cuda_runtime.h>

#define Ll 8
#define Kk 35
#define Sq 101
#define NP 51          // key pairs (50 full + 1 zero-padded odd slot)
#define PRS 36         // floats per pair row (32 used + 4 pad) = 144B, 16B aligned
#define BLOCK 128

#define KOFF 0
#define VOFF (NP * PRS)            // 1836
#define SKVTOT (2 * NP * PRS)      // 3672 floats (aliases x staging, 3500)

// shared-weight buffer offsets (floats)
#define OWQKV 0
#define OBQKV 768
#define OWO   816
#define OBO   1072
#define OW1   1088
#define OB1   1344
#define OW2   1360
#define OB2   1616
#define OG1   1632
#define OBE1  1648
#define OG2   1664
#define OBE2  1680
#define WTOT  1696

typedef unsigned long long u64;

__device__ __forceinline__ u64 pk2(float lo, float hi) {
    u64 r; asm("mov.b64 %0, {%1, %2};" : "=l"(r) : "f"(lo), "f"(hi)); return r;
}
__device__ __forceinline__ void upk2(u64 v, float& lo, float& hi) {
    asm("mov.b64 {%0, %1}, %2;" : "=f"(lo), "=f"(hi) : "l"(v));
}
__device__ __forceinline__ u64 fma2_(u64 a, u64 b, u64 c) {
    u64 d; asm("fma.rn.f32x2 %0, %1, %2, %3;" : "=l"(d) : "l"(a), "l"(b), "l"(c)); return d;
}
__device__ __forceinline__ u64 mul2_(u64 a, u64 b) {
    u64 d; asm("mul.rn.f32x2 %0, %1, %2;" : "=l"(d) : "l"(a), "l"(b)); return d;
}
__device__ __forceinline__ u64 add2_(u64 a, u64 b) {
    u64 d; asm("add.rn.f32x2 %0, %1, %2;" : "=l"(d) : "l"(a), "l"(b)); return d;
}
__device__ __forceinline__ float ex2_(float x) {
    float e; asm("ex2.approx.f32 %0, %1;" : "=f"(e) : "f"(x)); return e;
}

// dot of packed 16-vector a2[8] with a 16-float 16B-aligned row
__device__ __forceinline__ float dot16p(const u64* a2, const float* w) {
    const ulonglong2* w2 = reinterpret_cast<const ulonglong2*>(w);
    ulonglong2 p0 = w2[0], p1 = w2[1], p2 = w2[2], p3 = w2[3];
    u64 acc = mul2_(a2[0], p0.x);
    acc = fma2_(a2[1], p0.y, acc);
    acc = fma2_(a2[2], p1.x, acc);
    acc = fma2_(a2[3], p1.y, acc);
    acc = fma2_(a2[4], p2.x, acc);
    acc = fma2_(a2[5], p2.y, acc);
    acc = fma2_(a2[6], p3.x, acc);
    acc = fma2_(a2[7], p3.y, acc);
    float lo, hi; upk2(acc, lo, hi);
    return lo + hi;
}

__device__ __forceinline__ void ln16p(u64* io, const float* g, const float* b) {
    u64 s2 = io[0];
    #pragma unroll
    for (int i = 1; i < 8; i++) s2 = add2_(s2, io[i]);
    float slo, shi; upk2(s2, slo, shi);
    float mu = (slo + shi) * (1.f / 16.f);
    u64 nm2 = pk2(-mu, -mu);
    u64 c[8];
    #pragma unroll
    for (int i = 0; i < 8; i++) c[i] = add2_(io[i], nm2);
    u64 v2 = mul2_(c[0], c[0]);
    #pragma unroll
    for (int i = 1; i < 8; i++) v2 = fma2_(c[i], c[i], v2);
    float vlo, vhi; upk2(v2, vlo, vhi);
    float inv = rsqrtf((vlo + vhi) * (1.f / 16.f) + 1e-5f);
    u64 inv2 = pk2(inv, inv);
    const ulonglong2* g2 = reinterpret_cast<const ulonglong2*>(g);
    const ulonglong2* b2 = reinterpret_cast<const ulonglong2*>(b);
    #pragma unroll
    for (int j = 0; j < 4; j++) {
        ulonglong2 gg = g2[j], bb = b2[j];
        io[2*j]   = fma2_(mul2_(c[2*j],   inv2), gg.x, bb.x);
        io[2*j+1] = fma2_(mul2_(c[2*j+1], inv2), gg.y, bb.y);
    }
}

__global__ __launch_bounds__(BLOCK, 6) void TorrinE0_kernel(
    const float* __restrict__ x,
    const float* __restrict__ conv_w,
    const float* __restrict__ conv_b,
    const float* __restrict__ cls_emb,
    const float* __restrict__ Wqkv,
    const float* __restrict__ bqkv,
    const float* __restrict__ Wo,
    const float* __restrict__ bo,
    const float* __restrict__ W1,
    const float* __restrict__ b1,
    const float* __restrict__ W2,
    const float* __restrict__ b2,
    const float* __restrict__ ln1_g, const float* __restrict__ ln1_b,
    const float* __restrict__ ln2_g, const float* __restrict__ ln2_b,
    const float* __restrict__ lnf_g, const float* __restrict__ lnf_b,
    const float* __restrict__ end_w, const float* __restrict__ end_b,
    const float* __restrict__ head_w, const float* __restrict__ head_b,
    float* __restrict__ out)
{
    __shared__ __align__(16) float skv[SKVTOT];      // kT | vT (aliases x staging)
    __shared__ __align__(16) float sw[WTOT];
    __shared__ __align__(16) u64 shh[102 * 9];       // h2 stash, stride 9 u64
    __shared__ float sred[4];
    __shared__ float scls[16];

    const int b   = blockIdx.x;
    const int tid = threadIdx.x;
    const bool tok = (tid <= 100);

    // ---- stage x row + conv weights ----
    const float* xr = x + (size_t)b * 3500;
    for (int i = tid; i < 875; i += BLOCK)
        ((float4*)skv)[i] = ((const float4*)xr)[i];
    for (int i = tid; i < 140; i += BLOCK)
        ((float4*)sw)[i] = ((const float4*)conv_w)[i];
    if (tid < 16) sw[560 + tid] = conv_b[tid];
    __syncthreads();

    // ---- conv patchify -> packed h in registers ----
    u64 h2[8];
    if (tid == 0) {
        #pragma unroll
        for (int i = 0; i < 8; i++) h2[i] = pk2(cls_emb[2*i], cls_emb[2*i+1]);
    } else if (tok) {
        const float* ps = &skv[(tid - 1) * Kk];
        #pragma unroll
        for (int i = 0; i < 8; i++) {
            float a0 = sw[560 + 2*i], a1 = sw[560 + 2*i + 1];
            for (int k = 0; k < Kk; k++) {
                float p = ps[k];
                a0 += p * sw[(2*i) * Kk + k];
                a1 += p * sw[(2*i+1) * Kk + k];
            }
            h2[i] = pk2(a0, a1);
        }
    }
    __syncthreads();   // conv reads done before k/v overwrite

    const float QS = 0.70710678118654752f * 1.44269504088896340f;  // scale * log2(e)
    const int wbase = (tid >> 1) * PRS + (tid & 1);   // col parity = key parity

    #pragma unroll 1
    for (int l = 0; l < Ll; l++) {
        // ---- stage layer weights ----
        for (int i = tid; i < 192; i += BLOCK)
            ((float4*)&sw[OWQKV])[i] = ((const float4*)(Wqkv + l*768))[i];
        for (int i = tid; i < 64; i += BLOCK) {
            ((float4*)&sw[OWO])[i] = ((const float4*)(Wo + l*256))[i];
            ((float4*)&sw[OW1])[i] = ((const float4*)(W1 + l*256))[i];
            ((float4*)&sw[OW2])[i] = ((const float4*)(W2 + l*256))[i];
        }
        if (tid < 48) sw[OBQKV + tid] = bqkv[l*48 + tid];
        if (tid < 16) {
            sw[OBO  + tid] = bo[l*16 + tid];
            sw[OB1  + tid] = b1[l*16 + tid];
            sw[OB2  + tid] = b2[l*16 + tid];
            sw[OG1  + tid] = ln1_g[l*16 + tid];
            sw[OBE1 + tid] = ln1_b[l*16 + tid];
            sw[OG2  + tid] = ln2_g[l*16 + tid];
            sw[OBE2 + tid] = ln2_b[l*16 + tid];
        }
        __syncthreads();

        // ---- k/v projection -> transposed smem; stash h2 ----
        u64* st = &shh[tid * 9];
        if (tok) {
            #pragma unroll
            for (int h = 0; h < 8; h++) {
                float k0 = sw[OBQKV + 16 + 2*h]     + dot16p(h2, &sw[OWQKV + (16 + 2*h)*16]);
                float k1 = sw[OBQKV + 16 + 2*h + 1] + dot16p(h2, &sw[OWQKV + (17 + 2*h)*16]);
                skv[KOFF + wbase + 4*h]     = k0;
                skv[KOFF + wbase + 4*h + 2] = k1;
                float v0 = sw[OBQKV + 32 + 2*h]     + dot16p(h2, &sw[OWQKV + (32 + 2*h)*16]);
                float v1 = sw[OBQKV + 32 + 2*h + 1] + dot16p(h2, &sw[OWQKV + (33 + 2*h)*16]);
                skv[VOFF + wbase + 4*h]     = v0;
                skv[VOFF + wbase + 4*h + 2] = v1;
            }
            #pragma unroll
            for (int i = 0; i < 8; i++) st[i] = h2[i];   // stash: frees h2 for the hot loop
        } else if (tid == 101) {
            // zero-pad odd slot of pair 50: exp(0)=1 corrected post-loop; v=0
            #pragma unroll
            for (int h = 0; h < 8; h++) {
                skv[KOFF + wbase + 4*h]     = 0.f;
                skv[KOFF + wbase + 4*h + 2] = 0.f;
                skv[VOFF + wbase + 4*h]     = 0.f;
                skv[VOFF + wbase + 4*h + 2] = 0.f;
            }
        }
        __syncthreads();

        // ---- attention: 2 passes x 4 heads over 51 key-pairs (low reg pressure) ----
        if (tok) {
            u64 ctxp[8];

            #pragma unroll 1
            for (int pass = 0; pass < 2; pass++) {
                const int hb = pass * 4;

                // q projection for this pass's 4 heads (h2 reloaded from stash)
                u64 qb0[4], qb1[4];
                {
                    u64 ht[8];
                    #pragma unroll
                    for (int i = 0; i < 8; i++) ht[i] = st[i];
                    #pragma unroll
                    for (int i = 0; i < 4; i++) {
                        int h = hb + i;
                        float q0 = sw[OBQKV + 2*h]     + dot16p(ht, &sw[OWQKV + (2*h)*16]);
                        float q1 = sw[OBQKV + 2*h + 1] + dot16p(ht, &sw[OWQKV + (2*h+1)*16]);
                        q0 *= QS; q1 *= QS;
                        qb0[i] = pk2(q0, q0);
                        qb1[i] = pk2(q1, q1);
                    }
                }

                u64 ssum2[4], ctx0[4], ctx1[4];
                #pragma unroll
                for (int i = 0; i < 4; i++) { ssum2[i] = 0ULL; ctx0[i] = 0ULL; ctx1[i] = 0ULL; }

                const ulonglong2* kpp = (const ulonglong2*)&skv[KOFF] + hb;
                const ulonglong2* vpp = (const ulonglong2*)&skv[VOFF] + hb;
                #pragma unroll 1
                for (int p = 0; p < NP; p++) {
                    #pragma unroll
                    for (int i = 0; i < 4; i++) {
                        ulonglong2 kk = kpp[i];            // (k0e,k0o),(k1e,k1o)
                        u64 d2 = fma2_(qb1[i], kk.y, mul2_(qb0[i], kk.x));   // (se,so)
                        float se, so; upk2(d2, se, so);
                        float ee = ex2_(se), eo = ex2_(so);
                        u64 ep = pk2(ee, eo);
                        ssum2[i] = add2_(ssum2[i], ep);
                        ulonglong2 vv = vpp[i];
                        ctx0[i] = fma2_(ep, vv.x, ctx0[i]);
                        ctx1[i] = fma2_(ep, vv.y, ctx1[i]);
                    }
                    kpp += 9; vpp += 9;
                }

                #pragma unroll
                for (int i = 0; i < 4; i++) {
                    float slo, shi; upk2(ssum2[i], slo, shi);
                    float r = __fdividef(1.f, slo + shi - 1.f);   // remove pad's exp(0)=1
                    float a0, a1, b0v, b1v;
                    upk2(ctx0[i], a0, a1);
                    upk2(ctx1[i], b0v, b1v);
                    ctxp[hb + i] = pk2((a0 + a1) * r, (b0v + b1v) * r);
                }
            }

            #pragma unroll
            for (int i = 0; i < 8; i++) h2[i] = st[i];   // restore h

            // out projection + residual + LN1
            u64 nh2[8];
            #pragma unroll
            for (int o = 0; o < 8; o++) {
                float d0 = sw[OBO + 2*o]     + dot16p(ctxp, &sw[OWO + (2*o)*16]);
                float d1 = sw[OBO + 2*o + 1] + dot16p(ctxp, &sw[OWO + (2*o+1)*16]);
                nh2[o] = add2_(h2[o], pk2(d0, d1));
            }
            ln16p(nh2, &sw[OG1], &sw[OBE1]);
            #pragma unroll
            for (int i = 0; i < 8; i++) h2[i] = nh2[i];

            // FFN
            u64 ff2[8];
            #pragma unroll
            for (int f = 0; f < 8; f++) {
                float f0 = fmaxf(sw[OB1 + 2*f]     + dot16p(h2, &sw[OW1 + (2*f)*16]),   0.f);
                float f1 = fmaxf(sw[OB1 + 2*f + 1] + dot16p(h2, &sw[OW1 + (2*f+1)*16]), 0.f);
                ff2[f] = pk2(f0, f1);
            }
            #pragma unroll
            for (int o = 0; o < 8; o++) {
                float d0 = sw[OB2 + 2*o]     + dot16p(ff2, &sw[OW2 + (2*o)*16]);
                float d1 = sw[OB2 + 2*o + 1] + dot16p(ff2, &sw[OW2 + (2*o+1)*16]);
                nh2[o] = add2_(h2[o], pk2(d0, d1));
            }
            ln16p(nh2, &sw[OG2], &sw[OBE2]);
            #pragma unroll
            for (int i = 0; i < 8; i++) h2[i] = nh2[i];
        }
        __syncthreads();   // all reads of skv/sw done before next layer
    }

    // ---- final LN on CLS token + head ----
    if (tid == 0) {
        float hv[16];
        #pragma unroll
        for (int i = 0; i < 8; i++) upk2(h2[i], hv[2*i], hv[2*i+1]);
        float mu = 0.f;
        #pragma unroll
        for (int d = 0; d < 16; d++) mu += hv[d];
        mu *= (1.f/16.f);
        float var = 0.f;
        #pragma unroll
        for (int d = 0; d < 16; d++) { float c = hv[d] - mu; var += c*c; }
        var *= (1.f/16.f);
        float inv = rsqrtf(var + 1e-5f);
        #pragma unroll
        for (int d = 0; d < 16; d++)
            scls[d] = (hv[d] - mu) * inv * lnf_g[d] + lnf_b[d];
    }
    __syncthreads();

    float part = 0.f;
    if (tid < 100) {
        u64 c2[8];
        #pragma unroll
        for (int i = 0; i < 8; i++) c2[i] = pk2(scls[2*i], scls[2*i+1]);
        float acc = end_b[tid] + dot16p(c2, end_w + tid * 16);
        part = acc * head_w[tid];
    }
    #pragma unroll
    for (int off = 16; off > 0; off >>= 1)
        part += __shfl_down_sync(0xffffffffu, part, off);
    if ((tid & 31) == 0) sred[tid >> 5] = part;
    __syncthreads();
    if (tid == 0) {
        float z = sred[0] + sred[1] + sred[2] + sred[3] + head_b[0];
        out[b] = 1.f / (1.f + ex2_(-z * 1.44269504088896340f));
    }
}

extern "C" void kernel_launch(void* const* d_in, const int* in_sizes, int n_in,
                              void* d_out, int out_size) {
    const float* x      = (const float*)d_in[0];
    const float* conv_w = (const float*)d_in[1];
    const float* conv_b = (const float*)d_in[2];
    const float* cls_e  = (const float*)d_in[3];
    const float* Wqkv   = (const float*)d_in[4];
    const float* bqkv   = (const float*)d_in[5];
    const float* Wo     = (const float*)d_in[6];
    const float* bo     = (const float*)d_in[7];
    const float* W1     = (const float*)d_in[8];
    const float* b1     = (const float*)d_in[9];
    const float* W2     = (const float*)d_in[10];
    const float* b2     = (const float*)d_in[11];
    const float* ln1_g  = (const float*)d_in[12];
    const float* ln1_b  = (const float*)d_in[13];
    const float* ln2_g  = (const float*)d_in[14];
    const float* ln2_b  = (const float*)d_in[15];
    const float* lnf_g  = (const float*)d_in[16];
    const float* lnf_b  = (const float*)d_in[17];
    const float* end_w  = (const float*)d_in[18];
    const float* end_b  = (const float*)d_in[19];
    const float* head_w = (const float*)d_in[20];
    const float* head_b = (const float*)d_in[21];

    int B = out_size;   // 2048
    TorrinE0_kernel<<<B, BLOCK>>>(x, conv_w, conv_b, cls_e, Wqkv, bqkv, Wo, bo,
                                  W1, b1, W2, b2, ln1_g, ln1_b, ln2_g, ln2_b,
                                  lnf_g, lnf_b, end_w, end_b, head_w, head_b,
                                  (float*)d_out);
}

// round 10
// speedup vs baseline: 1.7631x; 1.5014x over previous
#include <cuda_runtime.h>
#include <cuda_fp16.h>

#define Ll 8
#define Kk 35
#define Sq 101
#define NP 51          // key pairs (50 full + 1 zero-padded odd slot)
#define BLOCK 128

// f16 k/v regions inside skv (u32 words): per pair 16 words (8 heads x 2 dims, f16x2 even/odd)
#define KWORDS (NP * 16)           // 816 u32
#define VWOFF  KWORDS              // v starts after k

// shared-weight buffer offsets (floats)
#define OWQKV 0
#define OBQKV 768
#define OWO   816
#define OBO   1072
#define OW1   1088
#define OB1   1344
#define OW2   1360
#define OB2   1616
#define OG1   1632
#define OBE1  1648
#define OG2   1664
#define OBE2  1680
#define WTOT  1696

typedef unsigned long long u64;
typedef unsigned int u32;

__device__ __forceinline__ u64 pk2(float lo, float hi) {
    u64 r; asm("mov.b64 %0, {%1, %2};" : "=l"(r) : "f"(lo), "f"(hi)); return r;
}
__device__ __forceinline__ void upk2(u64 v, float& lo, float& hi) {
    asm("mov.b64 {%0, %1}, %2;" : "=f"(lo), "=f"(hi) : "l"(v));
}
__device__ __forceinline__ u64 fma2_(u64 a, u64 b, u64 c) {
    u64 d; asm("fma.rn.f32x2 %0, %1, %2, %3;" : "=l"(d) : "l"(a), "l"(b), "l"(c)); return d;
}
__device__ __forceinline__ u64 mul2_(u64 a, u64 b) {
    u64 d; asm("mul.rn.f32x2 %0, %1, %2;" : "=l"(d) : "l"(a), "l"(b)); return d;
}
__device__ __forceinline__ u64 add2_(u64 a, u64 b) {
    u64 d; asm("add.rn.f32x2 %0, %1, %2;" : "=l"(d) : "l"(a), "l"(b)); return d;
}
__device__ __forceinline__ float ex2_(float x) {
    float e; asm("ex2.approx.f32 %0, %1;" : "=f"(e) : "f"(x)); return e;
}
// ---- f16x2 helpers (b32-register packed half pairs) ----
__device__ __forceinline__ u32 hmul2_(u32 a, u32 b) {
    u32 d; asm("mul.rn.f16x2 %0, %1, %2;" : "=r"(d) : "r"(a), "r"(b)); return d;
}
__device__ __forceinline__ u32 hfma2_(u32 a, u32 b, u32 c) {
    u32 d; asm("fma.rn.f16x2 %0, %1, %2, %3;" : "=r"(d) : "r"(a), "r"(b), "r"(c)); return d;
}
__device__ __forceinline__ u32 hadd2_(u32 a, u32 b) {
    u32 d; asm("add.rn.f16x2 %0, %1, %2;" : "=r"(d) : "r"(a), "r"(b)); return d;
}
__device__ __forceinline__ u32 hex2_(u32 x) {
    u32 e; asm("ex2.approx.f16x2 %0, %1;" : "=r"(e) : "r"(x)); return e;
}
__device__ __forceinline__ u32 cvtdup_(float x) {     // (x,x) as f16x2
    u32 d; asm("cvt.rn.f16x2.f32 %0, %1, %1;" : "=r"(d) : "f"(x)); return d;
}
__device__ __forceinline__ float hsum2f_(u32 h) {     // low+high as f32
    __half2 v = *reinterpret_cast<__half2*>(&h);
    return __low2float(v) + __high2float(v);
}

// dot of packed 16-vector a2[8] with a 16-float 16B-aligned row
__device__ __forceinline__ float dot16p(const u64* a2, const float* w) {
    const ulonglong2* w2 = reinterpret_cast<const ulonglong2*>(w);
    ulonglong2 p0 = w2[0], p1 = w2[1], p2 = w2[2], p3 = w2[3];
    u64 acc = mul2_(a2[0], p0.x);
    acc = fma2_(a2[1], p0.y, acc);
    acc = fma2_(a2[2], p1.x, acc);
    acc = fma2_(a2[3], p1.y, acc);
    acc = fma2_(a2[4], p2.x, acc);
    acc = fma2_(a2[5], p2.y, acc);
    acc = fma2_(a2[6], p3.x, acc);
    acc = fma2_(a2[7], p3.y, acc);
    float lo, hi; upk2(acc, lo, hi);
    return lo + hi;
}

__device__ __forceinline__ void ln16p(u64* io, const float* g, const float* b) {
    u64 s2 = io[0];
    #pragma unroll
    for (int i = 1; i < 8; i++) s2 = add2_(s2, io[i]);
    float slo, shi; upk2(s2, slo, shi);
    float mu = (slo + shi) * (1.f / 16.f);
    u64 nm2 = pk2(-mu, -mu);
    u64 c[8];
    #pragma unroll
    for (int i = 0; i < 8; i++) c[i] = add2_(io[i], nm2);
    u64 v2 = mul2_(c[0], c[0]);
    #pragma unroll
    for (int i = 1; i < 8; i++) v2 = fma2_(c[i], c[i], v2);
    float vlo, vhi; upk2(v2, vlo, vhi);
    float inv = rsqrtf((vlo + vhi) * (1.f / 16.f) + 1e-5f);
    u64 inv2 = pk2(inv, inv);
    const ulonglong2* g2 = reinterpret_cast<const ulonglong2*>(g);
    const ulonglong2* b2 = reinterpret_cast<const ulonglong2*>(b);
    #pragma unroll
    for (int j = 0; j < 4; j++) {
        ulonglong2 gg = g2[j], bb = b2[j];
        io[2*j]   = fma2_(mul2_(c[2*j],   inv2), gg.x, bb.x);
        io[2*j+1] = fma2_(mul2_(c[2*j+1], inv2), gg.y, bb.y);
    }
}

__global__ __launch_bounds__(BLOCK, 6) void TorrinE0_kernel(
    const float* __restrict__ x,
    const float* __restrict__ conv_w,
    const float* __restrict__ conv_b,
    const float* __restrict__ cls_emb,
    const float* __restrict__ Wqkv,
    const float* __restrict__ bqkv,
    const float* __restrict__ Wo,
    const float* __restrict__ bo,
    const float* __restrict__ W1,
    const float* __restrict__ b1,
    const float* __restrict__ W2,
    const float* __restrict__ b2,
    const float* __restrict__ ln1_g, const float* __restrict__ ln1_b,
    const float* __restrict__ ln2_g, const float* __restrict__ ln2_b,
    const float* __restrict__ lnf_g, const float* __restrict__ lnf_b,
    const float* __restrict__ end_w, const float* __restrict__ end_b,
    const float* __restrict__ head_w, const float* __restrict__ head_b,
    float* __restrict__ out)
{
    // first 1632 u32 hold f16 kT|vT during layers; whole array holds x during staging
    __shared__ __align__(16) float skv[3520];
    __shared__ __align__(16) float sw[WTOT];
    __shared__ __align__(16) u64 shh[102 * 9];       // h2 stash, stride 9 u64
    __shared__ float sred[4];
    __shared__ float scls[16];

    const int b   = blockIdx.x;
    const int tid = threadIdx.x;
    const bool tok = (tid <= 100);

    // ---- stage x row + conv weights ----
    const float* xr = x + (size_t)b * 3500;
    for (int i = tid; i < 875; i += BLOCK)
        ((float4*)skv)[i] = ((const float4*)xr)[i];
    for (int i = tid; i < 140; i += BLOCK)
        ((float4*)sw)[i] = ((const float4*)conv_w)[i];
    if (tid < 16) sw[560 + tid] = conv_b[tid];
    __syncthreads();

    // ---- conv patchify -> packed h in registers ----
    u64 h2[8];
    if (tid == 0) {
        #pragma unroll
        for (int i = 0; i < 8; i++) h2[i] = pk2(cls_emb[2*i], cls_emb[2*i+1]);
    } else if (tok) {
        const float* ps = &skv[(tid - 1) * Kk];
        #pragma unroll
        for (int i = 0; i < 8; i++) {
            float a0 = sw[560 + 2*i], a1 = sw[560 + 2*i + 1];
            for (int k = 0; k < Kk; k++) {
                float p = ps[k];
                a0 += p * sw[(2*i) * Kk + k];
                a1 += p * sw[(2*i+1) * Kk + k];
            }
            h2[i] = pk2(a0, a1);
        }
    }
    __syncthreads();   // conv reads done before k/v overwrite

    const float QS = 0.70710678118654752f * 1.44269504088896340f;  // scale * log2(e)
    // f16 half-index base: pair p = tid>>1, parity = tid&1; word w = 2h+d
    __half* kh = (__half*)skv;
    __half* vh = kh + 2 * KWORDS;     // after 816 u32 words
    const int hbase = (tid >> 1) * 32 + (tid & 1);

    #pragma unroll 1
    for (int l = 0; l < Ll; l++) {
        // ---- stage layer weights ----
        for (int i = tid; i < 192; i += BLOCK)
            ((float4*)&sw[OWQKV])[i] = ((const float4*)(Wqkv + l*768))[i];
        for (int i = tid; i < 64; i += BLOCK) {
            ((float4*)&sw[OWO])[i] = ((const float4*)(Wo + l*256))[i];
            ((float4*)&sw[OW1])[i] = ((const float4*)(W1 + l*256))[i];
            ((float4*)&sw[OW2])[i] = ((const float4*)(W2 + l*256))[i];
        }
        if (tid < 48) sw[OBQKV + tid] = bqkv[l*48 + tid];
        if (tid < 16) {
            sw[OBO  + tid] = bo[l*16 + tid];
            sw[OB1  + tid] = b1[l*16 + tid];
            sw[OB2  + tid] = b2[l*16 + tid];
            sw[OG1  + tid] = ln1_g[l*16 + tid];
            sw[OBE1 + tid] = ln1_b[l*16 + tid];
            sw[OG2  + tid] = ln2_g[l*16 + tid];
            sw[OBE2 + tid] = ln2_b[l*16 + tid];
        }
        __syncthreads();

        // ---- qkv projection: q -> f16x2 dup regs (pre-scaled), k/v -> f16 transposed smem ----
        u32 qb0[8], qb1[8];
        u64* st = &shh[tid * 9];
        if (tok) {
            #pragma unroll
            for (int h = 0; h < 8; h++) {
                float q0 = sw[OBQKV + 2*h]     + dot16p(h2, &sw[OWQKV + (2*h)*16]);
                float q1 = sw[OBQKV + 2*h + 1] + dot16p(h2, &sw[OWQKV + (2*h+1)*16]);
                qb0[h] = cvtdup_(q0 * QS);
                qb1[h] = cvtdup_(q1 * QS);
                float k0 = sw[OBQKV + 16 + 2*h]     + dot16p(h2, &sw[OWQKV + (16 + 2*h)*16]);
                float k1 = sw[OBQKV + 16 + 2*h + 1] + dot16p(h2, &sw[OWQKV + (17 + 2*h)*16]);
                kh[hbase + 4*h]     = __float2half_rn(k0);
                kh[hbase + 4*h + 2] = __float2half_rn(k1);
                float v0 = sw[OBQKV + 32 + 2*h]     + dot16p(h2, &sw[OWQKV + (32 + 2*h)*16]);
                float v1 = sw[OBQKV + 32 + 2*h + 1] + dot16p(h2, &sw[OWQKV + (33 + 2*h)*16]);
                vh[hbase + 4*h]     = __float2half_rn(v0);
                vh[hbase + 4*h + 2] = __float2half_rn(v1);
            }
            #pragma unroll
            for (int i = 0; i < 8; i++) st[i] = h2[i];   // stash h2 across the hot loop
        } else if (tid == 101) {
            // zero-pad odd slot of pair 50: s=0 -> e=2^0=1 exactly, corrected post-loop; v=0
            #pragma unroll
            for (int h = 0; h < 8; h++) {
                kh[hbase + 4*h]     = __ushort_as_half((unsigned short)0);
                kh[hbase + 4*h + 2] = __ushort_as_half((unsigned short)0);
                vh[hbase + 4*h]     = __ushort_as_half((unsigned short)0);
                vh[hbase + 4*h + 2] = __ushort_as_half((unsigned short)0);
            }
        }
        __syncthreads();

        // ---- attention: 8 heads, f16x2 over 51 key-pairs ----
        if (tok) {
            u32 ssum[8], ctx0[8], ctx1[8];
            #pragma unroll
            for (int i = 0; i < 8; i++) { ssum[i] = 0u; ctx0[i] = 0u; ctx1[i] = 0u; }

            const uint4* kb = (const uint4*)skv;               // 4 uint4 per pair
            const uint4* vb = kb + NP * 4;
            #pragma unroll 1
            for (int p = 0; p < NP; p++) {
                u32 kw[16], vw[16];
                *(uint4*)&kw[0]  = kb[0]; *(uint4*)&kw[4]  = kb[1];
                *(uint4*)&kw[8]  = kb[2]; *(uint4*)&kw[12] = kb[3];
                *(uint4*)&vw[0]  = vb[0]; *(uint4*)&vw[4]  = vb[1];
                *(uint4*)&vw[8]  = vb[2]; *(uint4*)&vw[12] = vb[3];
                #pragma unroll
                for (int h = 0; h < 8; h++) {
                    u32 s = hfma2_(qb1[h], kw[2*h+1], hmul2_(qb0[h], kw[2*h]));
                    u32 e = hex2_(s);
                    ssum[h] = hadd2_(ssum[h], e);
                    ctx0[h] = hfma2_(e, vw[2*h],   ctx0[h]);
                    ctx1[h] = hfma2_(e, vw[2*h+1], ctx1[h]);
                }
                kb += 4; vb += 4;
            }

            // finalize softmax in f32 (pad contributed e=1 to the odd half)
            u64 ctxp[8];
            #pragma unroll
            for (int h = 0; h < 8; h++) {
                float r = __fdividef(1.f, hsum2f_(ssum[h]) - 1.f);
                ctxp[h] = pk2(hsum2f_(ctx0[h]) * r, hsum2f_(ctx1[h]) * r);
            }

            #pragma unroll
            for (int i = 0; i < 8; i++) h2[i] = st[i];   // restore h

            // out projection + residual + LN1
            u64 nh2[8];
            #pragma unroll
            for (int o = 0; o < 8; o++) {
                float d0 = sw[OBO + 2*o]     + dot16p(ctxp, &sw[OWO + (2*o)*16]);
                float d1 = sw[OBO + 2*o + 1] + dot16p(ctxp, &sw[OWO + (2*o+1)*16]);
                nh2[o] = add2_(h2[o], pk2(d0, d1));
            }
            ln16p(nh2, &sw[OG1], &sw[OBE1]);
            #pragma unroll
            for (int i = 0; i < 8; i++) h2[i] = nh2[i];

            // FFN
            u64 ff2[8];
            #pragma unroll
            for (int f = 0; f < 8; f++) {
                float f0 = fmaxf(sw[OB1 + 2*f]     + dot16p(h2, &sw[OW1 + (2*f)*16]),   0.f);
                float f1 = fmaxf(sw[OB1 + 2*f + 1] + dot16p(h2, &sw[OW1 + (2*f+1)*16]), 0.f);
                ff2[f] = pk2(f0, f1);
            }
            #pragma unroll
            for (int o = 0; o < 8; o++) {
                float d0 = sw[OB2 + 2*o]     + dot16p(ff2, &sw[OW2 + (2*o)*16]);
                float d1 = sw[OB2 + 2*o + 1] + dot16p(ff2, &sw[OW2 + (2*o+1)*16]);
                nh2[o] = add2_(h2[o], pk2(d0, d1));
            }
            ln16p(nh2, &sw[OG2], &sw[OBE2]);
            #pragma unroll
            for (int i = 0; i < 8; i++) h2[i] = nh2[i];
        }
        __syncthreads();   // all reads of skv/sw done before next layer
    }

    // ---- final LN on CLS token + head ----
    if (tid == 0) {
        float hv[16];
        #pragma unroll
        for (int i = 0; i < 8; i++) upk2(h2[i], hv[2*i], hv[2*i+1]);
        float mu = 0.f;
        #pragma unroll
        for (int d = 0; d < 16; d++) mu += hv[d];
        mu *= (1.f/16.f);
        float var = 0.f;
        #pragma unroll
        for (int d = 0; d < 16; d++) { float c = hv[d] - mu; var += c*c; }
        var *= (1.f/16.f);
        float inv = rsqrtf(var + 1e-5f);
        #pragma unroll
        for (int d = 0; d < 16; d++)
            scls[d] = (hv[d] - mu) * inv * lnf_g[d] + lnf_b[d];
    }
    __syncthreads();

    float part = 0.f;
    if (tid < 100) {
        u64 c2[8];
        #pragma unroll
        for (int i = 0; i < 8; i++) c2[i] = pk2(scls[2*i], scls[2*i+1]);
        float acc = end_b[tid] + dot16p(c2, end_w + tid * 16);
        part = acc * head_w[tid];
    }
    #pragma unroll
    for (int off = 16; off > 0; off >>= 1)
        part += __shfl_down_sync(0xffffffffu, part, off);
    if ((tid & 31) == 0) sred[tid >> 5] = part;
    __syncthreads();
    if (tid == 0) {
        float z = sred[0] + sred[1] + sred[2] + sred[3] + head_b[0];
        out[b] = 1.f / (1.f + ex2_(-z * 1.44269504088896340f));
    }
}

extern "C" void kernel_launch(void* const* d_in, const int* in_sizes, int n_in,
                              void* d_out, int out_size) {
    const float* x      = (const float*)d_in[0];
    const float* conv_w = (const float*)d_in[1];
    const float* conv_b = (const float*)d_in[2];
    const float* cls_e  = (const float*)d_in[3];
    const float* Wqkv   = (const float*)d_in[4];
    const float* bqkv   = (const float*)d_in[5];
    const float* Wo     = (const float*)d_in[6];
    const float* bo     = (const float*)d_in[7];
    const float* W1     = (const float*)d_in[8];
    const float* b1     = (const float*)d_in[9];
    const float* W2     = (const float*)d_in[10];
    const float* b2     = (const float*)d_in[11];
    const float* ln1_g  = (const float*)d_in[12];
    const float* ln1_b  = (const float*)d_in[13];
    const float* ln2_g  = (const float*)d_in[14];
    const float* ln2_b  = (const float*)d_in[15];
    const float* lnf_g  = (const float*)d_in[16];
    const float* lnf_b  = (const float*)d_in[17];
    const float* end_w  = (const float*)d_in[18];
    const float* end_b  = (const float*)d_in[19];
    const float* head_w = (const float*)d_in[20];
    const float* head_b = (const float*)d_in[21];

    int B = out_size;   // 2048
    TorrinE0_kernel<<<B, BLOCK>>>(x, conv_w, conv_b, cls_e, Wqkv, bqkv, Wo, bo,
                                  W1, b1, W2, b2, ln1_g, ln1_b, ln2_g, ln2_b,
                                  lnf_g, lnf_b, end_w, end_b, head_w, head_b,
                                  (float*)d_out);
}